// round 7
// baseline (speedup 1.0000x reference)
#include <cuda_runtime.h>
#include <cuda_fp16.h>
#include <cuda_fp4.h>

// MXFP4 (E2M1) block fake-quant embedding gather — R7:
//   - cp.async.cg staging of 8 rows into SMEM: true MLP=8 with zero register
//     cost (R5/R6 showed ptxas collapses register-based front-batching)
//   - thread reads only its own cp.async bytes -> wait_group 0, NO barrier
//   - hardware E2M1 rounding via cuda_fp4.h intrinsics
// d_in[0]: int32 indices, 16384 tokens
// d_in[1]: float32 embedding table, (50257, 1024)
// d_out  : float32 (16384, 1024)

#define F        1024
#define TOK_CTA  8

__device__ __forceinline__ float2 fp4_pair(float x, float y, float inv) {
    float2 a = make_float2(x * inv, y * inv);
    __nv_fp4x2_storage_t p =
        __nv_cvt_float2_to_fp4x2(a, __NV_E2M1, cudaRoundNearest);
    __half2_raw hr = __nv_cvt_fp4x2_to_halfraw2(p, __NV_E2M1);
    __half2 h = *reinterpret_cast<__half2*>(&hr);
    return __half22float2(h);                      // exact grid values
}

__global__ void __launch_bounds__(256)
mxfp4_embed_kernel(const int* __restrict__ idx,
                   const float* __restrict__ emb,
                   float* __restrict__ out) {
    __shared__ float4 sbuf[TOK_CTA * 256];          // 32 KB

    const int t = threadIdx.x;                      // one float4 of a row
    const int base = blockIdx.x * TOK_CTA;

    // uniform index loads (L1 broadcast)
    int rows[TOK_CTA];
    #pragma unroll
    for (int j = 0; j < TOK_CTA; j++)
        rows[j] = __ldg(&idx[base + j]);

    // Stage 8 independent rows via cp.async.cg (16B each): in-flight data
    // lives in the LSU/smem pipe, not registers -> guaranteed MLP=8.
    #pragma unroll
    for (int j = 0; j < TOK_CTA; j++) {
        const float4* gp = reinterpret_cast<const float4*>(emb) +
                           (size_t)rows[j] * (F / 4) + t;
        unsigned sp = (unsigned)__cvta_generic_to_shared(&sbuf[j * 256 + t]);
        asm volatile("cp.async.cg.shared.global [%0], [%1], 16;"
                     :: "r"(sp), "l"(gp));
    }
    asm volatile("cp.async.commit_group;");
    asm volatile("cp.async.wait_group 0;");
    // No __syncthreads(): each thread consumes exactly the bytes it staged.

    float4* dst = reinterpret_cast<float4*>(out) + (size_t)base * (F / 4) + t;

    #pragma unroll
    for (int j = 0; j < TOK_CTA; j++) {
        float4 v = sbuf[j * 256 + t];

        float m = fmaxf(fmaxf(fabsf(v.x), fabsf(v.y)),
                        fmaxf(fabsf(v.z), fabsf(v.w)));
        #pragma unroll
        for (int o = 4; o > 0; o >>= 1)
            m = fmaxf(m, __shfl_xor_sync(0xFFFFFFFFu, m, o, 8));

        const float sc  = (m == 0.0f) ? 1.0f : m * (1.0f / 6.0f);
        const float inv = (m == 0.0f) ? 0.0f : __fdividef(6.0f, m);

        float2 g0 = fp4_pair(v.x, v.y, inv);
        float2 g1 = fp4_pair(v.z, v.w, inv);

        float4 r;
        r.x = g0.x * sc;
        r.y = g0.y * sc;
        r.z = g1.x * sc;
        r.w = g1.y * sc;

        dst[(size_t)j * (F / 4)] = r;
    }
}

extern "C" void kernel_launch(void* const* d_in, const int* in_sizes, int n_in,
                              void* d_out, int out_size) {
    const int*   idx = (const int*)d_in[0];
    const float* emb = (const float*)d_in[1];
    float*       out = (float*)d_out;

    const int tokens = in_sizes[0];              // 16384
    mxfp4_embed_kernel<<<tokens / TOK_CTA, 256>>>(idx, emb, out);
}

// round 8
// speedup vs baseline: 1.2197x; 1.2197x over previous
#include <cuda_runtime.h>
#include <cuda_fp16.h>
#include <cuda_fp4.h>

// MXFP4 (E2M1) block fake-quant embedding gather — R8:
//   - R5 body (fastest measured; MLP proven irrelevant in R6/R7)
//   - st.global.cs streaming stores: output is write-once, keep it from
//     displacing the L2-resident embedding table
//   - hardware E2M1 rounding via cuda_fp4.h intrinsics
// d_in[0]: int32 indices, 16384 tokens
// d_in[1]: float32 embedding table, (50257, 1024)
// d_out  : float32 (16384, 1024)

#define F        1024
#define TOK_CTA  8

__device__ __forceinline__ float2 fp4_pair(float x, float y, float inv) {
    float2 a = make_float2(x * inv, y * inv);
    __nv_fp4x2_storage_t p =
        __nv_cvt_float2_to_fp4x2(a, __NV_E2M1, cudaRoundNearest);
    __half2_raw hr = __nv_cvt_fp4x2_to_halfraw2(p, __NV_E2M1);
    __half2 h = *reinterpret_cast<__half2*>(&hr);
    return __half22float2(h);                      // exact grid values
}

__global__ void __launch_bounds__(256)
mxfp4_embed_kernel(const int* __restrict__ idx,
                   const float* __restrict__ emb,
                   float* __restrict__ out) {
    const int t = threadIdx.x;                      // one float4 of a row
    const int base = blockIdx.x * TOK_CTA;

    // uniform index loads (L1 broadcast)
    int rows[TOK_CTA];
    #pragma unroll
    for (int j = 0; j < TOK_CTA; j++)
        rows[j] = __ldg(&idx[base + j]);

    float4 v[TOK_CTA];
    #pragma unroll
    for (int j = 0; j < TOK_CTA; j++)
        v[j] = __ldg(reinterpret_cast<const float4*>(emb) +
                     (size_t)rows[j] * (F / 4) + t);

    float4* dst = reinterpret_cast<float4*>(out) + (size_t)base * (F / 4) + t;

    #pragma unroll
    for (int j = 0; j < TOK_CTA; j++) {
        float m = fmaxf(fmaxf(fabsf(v[j].x), fabsf(v[j].y)),
                        fmaxf(fabsf(v[j].z), fabsf(v[j].w)));
        #pragma unroll
        for (int o = 4; o > 0; o >>= 1)
            m = fmaxf(m, __shfl_xor_sync(0xFFFFFFFFu, m, o, 8));

        const float sc  = (m == 0.0f) ? 1.0f : m * (1.0f / 6.0f);
        const float inv = (m == 0.0f) ? 0.0f : __fdividef(6.0f, m);

        float2 g0 = fp4_pair(v[j].x, v[j].y, inv);
        float2 g1 = fp4_pair(v[j].z, v[j].w, inv);

        float4 r;
        r.x = g0.x * sc;
        r.y = g0.y * sc;
        r.z = g1.x * sc;
        r.w = g1.y * sc;

        // streaming store: evict-first, don't pollute L2's table residency
        __stcs(dst + (size_t)j * (F / 4), r);
    }
}

extern "C" void kernel_launch(void* const* d_in, const int* in_sizes, int n_in,
                              void* d_out, int out_size) {
    const int*   idx = (const int*)d_in[0];
    const float* emb = (const float*)d_in[1];
    float*       out = (float*)d_out;

    const int tokens = in_sizes[0];              // 16384
    mxfp4_embed_kernel<<<tokens / TOK_CTA, 256>>>(idx, emb, out);
}

// round 9
// speedup vs baseline: 1.3153x; 1.0784x over previous
#include <cuda_runtime.h>
#include <cuda_fp16.h>
#include <cuda_fp4.h>

// MXFP4 (E2M1) block fake-quant embedding gather — R9:
//   - TOK_CTA=16 -> grid=1024 < 1184 resident CTAs: SINGLE wave, no transition
//   - st.global.cs streaming stores (R8 win: clean write drain)
//   - hardware E2M1 rounding via cuda_fp4.h intrinsics
// Model: kernel is at the HBM write-direction ceiling (~3.7-4 TB/s of pure
// writes = 67 MB output); reads are steady-state L2 hits. Only tail/wave
// overhead left to trim.
// d_in[0]: int32 indices, 16384 tokens
// d_in[1]: float32 embedding table, (50257, 1024)
// d_out  : float32 (16384, 1024)

#define F        1024
#define TOK_CTA  16

__device__ __forceinline__ float2 fp4_pair(float x, float y, float inv) {
    float2 a = make_float2(x * inv, y * inv);
    __nv_fp4x2_storage_t p =
        __nv_cvt_float2_to_fp4x2(a, __NV_E2M1, cudaRoundNearest);
    __half2_raw hr = __nv_cvt_fp4x2_to_halfraw2(p, __NV_E2M1);
    __half2 h = *reinterpret_cast<__half2*>(&hr);
    return __half22float2(h);                      // exact grid values
}

__global__ void __launch_bounds__(256)
mxfp4_embed_kernel(const int* __restrict__ idx,
                   const float* __restrict__ emb,
                   float* __restrict__ out) {
    const int t = threadIdx.x;                      // one float4 of a row
    const int base = blockIdx.x * TOK_CTA;

    // uniform index loads (L1 broadcast)
    int rows[TOK_CTA];
    #pragma unroll
    for (int j = 0; j < TOK_CTA; j++)
        rows[j] = __ldg(&idx[base + j]);

    float4* dst = reinterpret_cast<float4*>(out) + (size_t)base * (F / 4) + t;

    #pragma unroll
    for (int j = 0; j < TOK_CTA; j++) {
        float4 v = __ldg(reinterpret_cast<const float4*>(emb) +
                         (size_t)rows[j] * (F / 4) + t);

        float m = fmaxf(fmaxf(fabsf(v.x), fabsf(v.y)),
                        fmaxf(fabsf(v.z), fabsf(v.w)));
        #pragma unroll
        for (int o = 4; o > 0; o >>= 1)
            m = fmaxf(m, __shfl_xor_sync(0xFFFFFFFFu, m, o, 8));

        const float sc  = (m == 0.0f) ? 1.0f : m * (1.0f / 6.0f);
        const float inv = (m == 0.0f) ? 0.0f : __fdividef(6.0f, m);

        float2 g0 = fp4_pair(v.x, v.y, inv);
        float2 g1 = fp4_pair(v.z, v.w, inv);

        float4 r;
        r.x = g0.x * sc;
        r.y = g0.y * sc;
        r.z = g1.x * sc;
        r.w = g1.y * sc;

        // streaming store: evict-first, clean writeback drain
        __stcs(dst + (size_t)j * (F / 4), r);
    }
}

extern "C" void kernel_launch(void* const* d_in, const int* in_sizes, int n_in,
                              void* d_out, int out_size) {
    const int*   idx = (const int*)d_in[0];
    const float* emb = (const float*)d_in[1];
    float*       out = (float*)d_out;

    const int tokens = in_sizes[0];              // 16384
    mxfp4_embed_kernel<<<tokens / TOK_CTA, 256>>>(idx, emb, out);
}